// round 5
// baseline (speedup 1.0000x reference)
#include <cuda_runtime.h>
#include <cuda_bf16.h>
#include <math.h>
#include <stdint.h>

// ---------------- constants ----------------
#define BATCH   2
#define SEQ     4096
#define ROWS    (BATCH*SEQ)        // 8192
#define DMODEL  2048
#define DSTATE  64
#define DHEAD   64
#define NHEADS  32
#define CHUNK   64
#define NCHUNK  (SEQ/CHUNK)        // 64
#define CONVD   6144
#define ZXB_LD  8192               // cols we compute of zxbcdt (dt cols unused)
#define RMS_EPS 1.1920929e-07f

// ---------------- scratch ----------------
__device__ float    g_zxbc[(size_t)ROWS * ZXB_LD];
__device__ float    g_xbca[(size_t)ROWS * CONVD];
__device__ float    g_y   [(size_t)ROWS * DMODEL];
__device__ unsigned g_yn  [(size_t)ROWS * DMODEL];
__device__ float    g_cs  [(size_t)BATCH*NHEADS*NCHUNK*DSTATE];
__device__ float    g_prev[(size_t)BATCH*NHEADS*NCHUNK*DSTATE];
__device__ unsigned g_ut  [(size_t)ROWS * DMODEL];
__device__ unsigned g_wit [(size_t)ZXB_LD * DMODEL];
__device__ unsigned g_wot [(size_t)DMODEL * DMODEL];

// ---------------- helpers ----------------
__device__ __forceinline__ unsigned f2tf(float x) {
    unsigned r; asm("cvt.rna.tf32.f32 %0, %1;" : "=r"(r) : "f"(x)); return r;
}
__device__ __forceinline__ void cp16(void* dst, const void* src) {
    unsigned saddr = (unsigned)__cvta_generic_to_shared(dst);
    asm volatile("cp.async.cg.shared.global [%0], [%1], 16;" :: "r"(saddr), "l"(src));
}

// elementwise fp32 -> tf32 bits
__global__ void tf32_convert(const float* __restrict__ in, unsigned* __restrict__ out, size_t n4)
{
    size_t i = (size_t)blockIdx.x * blockDim.x + threadIdx.x;
    if (i >= n4) return;
    float4 v = ((const float4*)in)[i];
    uint4 o;
    o.x = f2tf(v.x); o.y = f2tf(v.y); o.z = f2tf(v.z); o.w = f2tf(v.w);
    ((uint4*)out)[i] = o;
}

// ============================================================================
// GEMM: C[M,N] = A[M,K] * B[N,K]^T ; A,B tf32 bits (u32), row-major.
// Block 128x256, K-tile 32, 256 threads = 8 warps (2m x 4n), warp tile 64x64,
// mma m16n8k8 grid 4x8 per warp. 3-stage cp.async ring. 1.0 LDS per MMA.
// ============================================================================
#define NSTG  3
#define ASZ   (128 * 36)            // u32 per A stage
#define BSZ   (256 * 36)            // u32 per B stage
#define STG   (ASZ + BSZ)           // 13824 u32 per stage
#define GSMEM (NSTG * STG * 4)      // 165888 B

__global__ __launch_bounds__(256, 1) void gemm_tn_tf32(
    const unsigned* __restrict__ A, const unsigned* __restrict__ B,
    float* __restrict__ C, int M, int N, int K)
{
    extern __shared__ __align__(16) unsigned sm[];

    const int tid  = threadIdx.x;
    const int row0 = blockIdx.y * 128;
    const int col0 = blockIdx.x * 256;
    const int warp = tid >> 5, lane = tid & 31;
    const int wm = warp >> 2, wn = warp & 3;   // 2 x 4 warp grid, warp tile 64x64
    const int g  = lane >> 2, tg = lane & 3;

    float acc[4][8][4];
#pragma unroll
    for (int i = 0; i < 4; i++)
#pragma unroll
        for (int j = 0; j < 8; j++)
#pragma unroll
            for (int k = 0; k < 4; k++) acc[i][j][k] = 0.f;

    const int lr = tid >> 3;          // 0..31 (row group)
    const int lc = (tid & 7) * 4;     // u32 col, 16B aligned

    const unsigned* Ag = A + (size_t)row0 * K;
    const unsigned* Bg = B + (size_t)col0 * K;
    const int NT = K >> 5;

    // issue K-tile j into stage j % NSTG
    auto issue = [&](int j) {
        unsigned* as = sm + (j % NSTG) * STG;
        unsigned* bs = as + ASZ;
        int k0 = j * 32;
#pragma unroll
        for (int i = 0; i < 4; i++) {          // A: 128 rows x 8 chunks
            int r = i * 32 + lr;
            cp16(&as[r * 36 + lc], Ag + (size_t)r * K + k0 + lc);
        }
#pragma unroll
        for (int i = 0; i < 8; i++) {          // B: 256 rows x 8 chunks
            int r = i * 32 + lr;
            cp16(&bs[r * 36 + lc], Bg + (size_t)r * K + k0 + lc);
        }
        asm volatile("cp.async.commit_group;");
    };

    issue(0);
    if (NT > 1) issue(1);

    for (int t = 0; t < NT; t++) {
        if (t + 2 < NT) {
            issue(t + 2);
            asm volatile("cp.async.wait_group 2;");
        } else if (t + 1 < NT) {
            asm volatile("cp.async.wait_group 1;");
        } else {
            asm volatile("cp.async.wait_group 0;");
        }
        __syncthreads();

        const unsigned* As = sm + (t % NSTG) * STG;
        const unsigned* Bs = As + ASZ;

#pragma unroll
        for (int kk = 0; kk < 32; kk += 8) {
            unsigned a[4][4], bf[8][2];
#pragma unroll
            for (int mt = 0; mt < 4; mt++) {
                int r = wm * 64 + mt * 16 + g;
                a[mt][0] = As[r * 36 + kk + tg];
                a[mt][1] = As[(r + 8) * 36 + kk + tg];
                a[mt][2] = As[r * 36 + kk + tg + 4];
                a[mt][3] = As[(r + 8) * 36 + kk + tg + 4];
            }
#pragma unroll
            for (int nt = 0; nt < 8; nt++) {
                int cn = wn * 64 + nt * 8 + g;
                bf[nt][0] = Bs[cn * 36 + kk + tg];
                bf[nt][1] = Bs[cn * 36 + kk + tg + 4];
            }
#pragma unroll
            for (int mt = 0; mt < 4; mt++)
#pragma unroll
                for (int nt = 0; nt < 8; nt++)
                    asm volatile(
                        "mma.sync.aligned.m16n8k8.row.col.f32.tf32.tf32.f32 "
                        "{%0,%1,%2,%3}, {%4,%5,%6,%7}, {%8,%9}, {%0,%1,%2,%3};"
                        : "+f"(acc[mt][nt][0]), "+f"(acc[mt][nt][1]),
                          "+f"(acc[mt][nt][2]), "+f"(acc[mt][nt][3])
                        : "r"(a[mt][0]), "r"(a[mt][1]), "r"(a[mt][2]), "r"(a[mt][3]),
                          "r"(bf[nt][0]), "r"(bf[nt][1]));
        }
        __syncthreads();
    }

#pragma unroll
    for (int mt = 0; mt < 4; mt++) {
        int r = row0 + wm * 64 + mt * 16 + g;
#pragma unroll
        for (int nt = 0; nt < 8; nt++) {
            int cc = col0 + wn * 64 + nt * 8 + 2 * tg;
            *(float2*)&C[(size_t)r * N + cc]       = make_float2(acc[mt][nt][0], acc[mt][nt][1]);
            *(float2*)&C[(size_t)(r + 8) * N + cc] = make_float2(acc[mt][nt][2], acc[mt][nt][3]);
        }
    }
}

// ============================================================================
// Depthwise conv(3) + bias + SiLU over xBC channels (cols 2048..8191 of zxbc)
// ============================================================================
__global__ void conv_silu_kernel(const float* __restrict__ zxbc,
                                 const float* __restrict__ cw,
                                 const float* __restrict__ cb,
                                 float* __restrict__ out)
{
    int ch = blockIdx.x * blockDim.x + threadIdx.x;
    int r  = blockIdx.y;
    if (ch >= CONVD) return;
    int l = r & (SEQ - 1);
    const float* col = zxbc + DMODEL + ch;
    float xm = (l > 0)       ? col[(size_t)(r - 1) * ZXB_LD] : 0.f;
    float x0 =                 col[(size_t)r       * ZXB_LD];
    float xp = (l < SEQ - 1) ? col[(size_t)(r + 1) * ZXB_LD] : 0.f;
    float v = fmaf(cw[ch * 3], xm, fmaf(cw[ch * 3 + 1], x0, fmaf(cw[ch * 3 + 2], xp, cb[ch])));
    out[(size_t)r * CONVD + ch] = v / (1.f + expf(-v));
}

// ============================================================================
// Per-chunk SSD
// ============================================================================
__global__ __launch_bounds__(256) void ssd_chunk_kernel(const float* __restrict__ xbca,
                                                        float* __restrict__ ydiag,
                                                        float* __restrict__ cs)
{
    __shared__ float Bs[64][64];
    __shared__ float Cs[64][64];
    __shared__ float Gs[64][64];

    int bid = blockIdx.x;
    int c  = bid & 63;
    int bh = bid >> 6;
    int h  = bh & 31;
    int b  = bh >> 5;
    size_t row0 = (size_t)(b * SEQ + c * CHUNK) * CONVD;
    int tid = threadIdx.x;

    for (int i = tid; i < 64 * 16; i += 256) {
        int l = i >> 4, q = (i & 15) * 4;
        *(float4*)&Bs[l][q] = *(const float4*)&xbca[row0 + (size_t)l * CONVD + DMODEL + h * 64 + q];
        *(float4*)&Cs[l][q] = *(const float4*)&xbca[row0 + (size_t)l * CONVD + 2 * DMODEL + h * 64 + q];
    }
    __syncthreads();

    int l  = tid >> 2;
    int m0 = tid & 3;
    for (int m = m0; m <= l; m += 4) {
        float a = 0.f;
#pragma unroll 8
        for (int n = 0; n < 64; n++) a += Cs[l][n] * Bs[m][n];
        Gs[l][m] = a;
    }
    __syncthreads();

    for (int i = tid; i < 64 * 16; i += 256) {
        int ll = i >> 4, q = (i & 15) * 4;
        *(float4*)&Cs[ll][q] = *(const float4*)&xbca[row0 + (size_t)ll * CONVD + h * 64 + q];
    }
    __syncthreads();

    for (int p = m0; p < 64; p += 4) {
        float a = 0.f;
        for (int m = 0; m <= l; m++) a += Gs[l][m] * Cs[m][p];
        ydiag[(size_t)(b * SEQ + c * CHUNK + l) * DMODEL + h * 64 + p] = a;
    }

    if (tid < 64) {
        float a = 0.f;
#pragma unroll 8
        for (int ll = 0; ll < 64; ll++) a += Cs[ll][tid] * Bs[ll][tid];
        cs[(size_t)bid * 64 + tid] = a;
    }
}

// ============================================================================
// Inter-chunk scan (constant decay exp(63*A_log[h]) per head)
// ============================================================================
__global__ void scan_kernel(const float* __restrict__ cs, const float* __restrict__ A_log,
                            float* __restrict__ prev)
{
    int bh = blockIdx.x;
    int h  = bh & 31;
    int n  = threadIdx.x;
    float d = expf(63.f * A_log[h]);
    float s = 0.f;
    for (int c = 0; c < NCHUNK; c++) {
        size_t idx = ((size_t)bh * NCHUNK + c) * 64 + n;
        prev[idx] = s;
        s = s * d + cs[idx];
    }
}

// ============================================================================
// Y = Y_diag + Y_off; gate with silu(z); RMSNorm. Output tf32 bits.
// ============================================================================
__global__ __launch_bounds__(256) void combine_kernel(
    const float* __restrict__ ydiag, const float* __restrict__ zxbc,
    const float* __restrict__ xbca,  const float* __restrict__ prev,
    const float* __restrict__ rms_w, unsigned* __restrict__ yn)
{
    int r = blockIdx.x;
    int b = r >> 12;
    int l = r & (SEQ - 1);
    int c = l >> 6;

    __shared__ float sh_yoff[NHEADS];
    __shared__ float sh_red[8];

    int tid = threadIdx.x, warp = tid >> 5, lane = tid & 31;

    for (int h = warp; h < NHEADS; h += 8) {
        const float* Crow = xbca + (size_t)r * CONVD + 2 * DMODEL + h * 64;
        const float* pv   = prev + ((size_t)(b * NHEADS + h) * NCHUNK + c) * 64;
        int n0 = lane * 2;
        float v = Crow[n0] * pv[n0] + Crow[n0 + 1] * pv[n0 + 1];
#pragma unroll
        for (int o = 16; o; o >>= 1) v += __shfl_down_sync(0xffffffffu, v, o);
        if (lane == 0) sh_yoff[h] = v;
    }
    __syncthreads();

    float vals[8];
    float ss = 0.f;
#pragma unroll
    for (int j = 0; j < 8; j++) {
        int d = tid + j * 256;
        float z  = zxbc[(size_t)r * ZXB_LD + d];
        float sz = z / (1.f + expf(-z));
        float y  = (ydiag[(size_t)r * DMODEL + d] + sh_yoff[d >> 6]) * sz;
        vals[j] = y;
        ss += y * y;
    }
#pragma unroll
    for (int o = 16; o; o >>= 1) ss += __shfl_down_sync(0xffffffffu, ss, o);
    if (lane == 0) sh_red[warp] = ss;
    __syncthreads();
    if (tid == 0) {
        float t = 0.f;
#pragma unroll
        for (int w = 0; w < 8; w++) t += sh_red[w];
        sh_red[0] = rsqrtf(t / (float)DMODEL + RMS_EPS);
    }
    __syncthreads();
    float scale = sh_red[0];
#pragma unroll
    for (int j = 0; j < 8; j++) {
        int d = tid + j * 256;
        yn[(size_t)r * DMODEL + d] = f2tf(vals[j] * scale * rms_w[d]);
    }
}

// ============================================================================
// launch
// ============================================================================
extern "C" void kernel_launch(void* const* d_in, const int* in_sizes, int n_in,
                              void* d_out, int out_size)
{
    const float* u      = (const float*)d_in[0];
    const float* W_in   = (const float*)d_in[1];
    const float* W_out  = (const float*)d_in[2];
    const float* conv_w = (const float*)d_in[3];
    const float* conv_b = (const float*)d_in[4];
    const float* A_log  = (const float*)d_in[5];
    const float* rms_w  = (const float*)d_in[6];
    float* out = (float*)d_out;

    float *zxbc, *xbca, *y, *cs, *prev;
    unsigned *yn, *ut, *wit, *wot;
    cudaGetSymbolAddress((void**)&zxbc, g_zxbc);
    cudaGetSymbolAddress((void**)&xbca, g_xbca);
    cudaGetSymbolAddress((void**)&y,    g_y);
    cudaGetSymbolAddress((void**)&yn,   g_yn);
    cudaGetSymbolAddress((void**)&cs,   g_cs);
    cudaGetSymbolAddress((void**)&prev, g_prev);
    cudaGetSymbolAddress((void**)&ut,   g_ut);
    cudaGetSymbolAddress((void**)&wit,  g_wit);
    cudaGetSymbolAddress((void**)&wot,  g_wot);

    static bool attr_done = false;
    if (!attr_done) {
        cudaFuncSetAttribute(gemm_tn_tf32, cudaFuncAttributeMaxDynamicSharedMemorySize, GSMEM);
        attr_done = true;
    }

    // 0) convert operands to tf32 bits
    {
        size_t n4u = (size_t)ROWS * DMODEL / 4;
        tf32_convert<<<(unsigned)((n4u + 255) / 256), 256>>>(u, ut, n4u);
        size_t n4w = (size_t)ZXB_LD * DMODEL / 4;
        tf32_convert<<<(unsigned)((n4w + 255) / 256), 256>>>(W_in, wit, n4w);
        size_t n4o = (size_t)DMODEL * DMODEL / 4;
        tf32_convert<<<(unsigned)((n4o + 255) / 256), 256>>>(W_out, wot, n4o);
    }
    // 1) zxbc = u @ W_in^T (first 8192 output cols)
    gemm_tn_tf32<<<dim3(ZXB_LD / 256, ROWS / 128), 256, GSMEM>>>(ut, wit, zxbc, ROWS, ZXB_LD, DMODEL);
    // 2) depthwise conv + silu
    conv_silu_kernel<<<dim3(CONVD / 256, ROWS), 256>>>(zxbc, conv_w, conv_b, xbca);
    // 3) per-chunk SSD
    ssd_chunk_kernel<<<BATCH * NHEADS * NCHUNK, 256>>>(xbca, y, cs);
    // 4) inter-chunk scan
    scan_kernel<<<BATCH * NHEADS, 64>>>(cs, A_log, prev);
    // 5) Y_off + gate + rmsnorm (writes tf32 bits)
    combine_kernel<<<ROWS, 256>>>(y, zxbc, xbca, prev, rms_w, yn);
    // 6) out = yn @ W_out^T
    gemm_tn_tf32<<<dim3(DMODEL / 256, ROWS / 128), 256, GSMEM>>>(yn, wot, out, ROWS, DMODEL, DMODEL);
}

// round 6
// speedup vs baseline: 1.4643x; 1.4643x over previous
#include <cuda_runtime.h>
#include <cuda_fp16.h>
#include <math.h>
#include <stdint.h>

// ---------------- constants ----------------
#define BATCH   2
#define SEQ     4096
#define ROWS    (BATCH*SEQ)        // 8192
#define DMODEL  2048
#define DSTATE  64
#define DHEAD   64
#define NHEADS  32
#define CHUNK   64
#define NCHUNK  (SEQ/CHUNK)        // 64
#define CONVD   6144
#define ZXB_LD  8192               // cols we compute of zxbcdt (dt cols unused)
#define RMS_EPS 1.1920929e-07f

// ---------------- scratch ----------------
__device__ float  g_zxbc[(size_t)ROWS * ZXB_LD];
__device__ float  g_xbca[(size_t)ROWS * CONVD];
__device__ float  g_y   [(size_t)ROWS * DMODEL];
__device__ __half g_yn  [(size_t)ROWS * DMODEL];    // gated+rmsnormed, fp16
__device__ float  g_cs  [(size_t)BATCH*NHEADS*NCHUNK*DSTATE];
__device__ float  g_prev[(size_t)BATCH*NHEADS*NCHUNK*DSTATE];
__device__ __half g_ut  [(size_t)ROWS * DMODEL];    // u in fp16
__device__ __half g_wit [(size_t)ZXB_LD * DMODEL];  // W_in rows 0..8191, fp16
__device__ __half g_wot [(size_t)DMODEL * DMODEL];  // W_out, fp16

// ---------------- helpers ----------------
__device__ __forceinline__ void cp16(void* dst, const void* src) {
    unsigned saddr = (unsigned)__cvta_generic_to_shared(dst);
    asm volatile("cp.async.cg.shared.global [%0], [%1], 16;" :: "r"(saddr), "l"(src));
}

// elementwise fp32 -> fp16 (reads float4, writes 4 halves = uint2)
__global__ void h_convert(const float* __restrict__ in, __half* __restrict__ out, size_t n4)
{
    size_t i = (size_t)blockIdx.x * blockDim.x + threadIdx.x;
    if (i >= n4) return;
    float4 v = ((const float4*)in)[i];
    __half2 lo = __floats2half2_rn(v.x, v.y);
    __half2 hi = __floats2half2_rn(v.z, v.w);
    uint2 o;
    o.x = *(unsigned*)&lo;
    o.y = *(unsigned*)&hi;
    ((uint2*)out)[i] = o;
}

// ============================================================================
// GEMM: C[M,N] = A[M,K] * B[N,K]^T ; A,B fp16, row-major; fp32 accumulate.
// Block 128x128, K-tile 32 halfs, 256 threads = 8 warps (2m x 4n),
// warp tile 64x32, mma m16n8k16 grid 4x4 per warp, 2 k-steps per tile.
// 3-stage cp.async ring. Row stride 20 u32 (16 data half2 + 4 pad): LDS
// fragment loads are bank-conflict-free for all phases.
// ============================================================================
#define NSTG  3
#define RSTR  20                    // u32 per smem row
#define ASZ   (128 * RSTR)          // u32 per A stage (2560)
#define STG   (2 * ASZ)             // A + B per stage (5120 u32 = 20KB)
#define GSMEM (NSTG * STG * 4)      // 61440 B

__global__ __launch_bounds__(256, 2) void gemm_tn_f16(
    const __half* __restrict__ A, const __half* __restrict__ B,
    float* __restrict__ C, int M, int N, int K)
{
    extern __shared__ __align__(16) unsigned sm[];

    const int tid  = threadIdx.x;
    const int row0 = blockIdx.y * 128;
    const int col0 = blockIdx.x * 128;
    const int warp = tid >> 5, lane = tid & 31;
    const int wm = warp >> 2, wn = warp & 3;   // 2 x 4 warp grid
    const int g  = lane >> 2, tg = lane & 3;

    float acc[4][4][4];
#pragma unroll
    for (int i = 0; i < 4; i++)
#pragma unroll
        for (int j = 0; j < 4; j++)
#pragma unroll
            for (int k = 0; k < 4; k++) acc[i][j][k] = 0.f;

    const __half* Ag = A + (size_t)row0 * K;
    const __half* Bg = B + (size_t)col0 * K;
    const int NT = K >> 5;             // K-tiles of 32 halfs

    // fill stage j%NSTG with K-tile j. 128 rows x 4 chunks(16B) per matrix.
    auto issue = [&](int j) {
        unsigned* as = sm + (j % NSTG) * STG;
        unsigned* bs = as + ASZ;
        int k0 = j * 32;
#pragma unroll
        for (int i = 0; i < 2; i++) {
            int ch = tid + i * 256;          // 0..511
            int r = ch >> 2, c = ch & 3;
            cp16(&as[r * RSTR + c * 4], Ag + (size_t)r * K + k0 + c * 8);
        }
#pragma unroll
        for (int i = 0; i < 2; i++) {
            int ch = tid + i * 256;
            int r = ch >> 2, c = ch & 3;
            cp16(&bs[r * RSTR + c * 4], Bg + (size_t)r * K + k0 + c * 8);
        }
        asm volatile("cp.async.commit_group;");
    };

    issue(0);
    if (NT > 1) issue(1);

    for (int t = 0; t < NT; t++) {
        if (t + 2 < NT) {
            issue(t + 2);
            asm volatile("cp.async.wait_group 2;");
        } else if (t + 1 < NT) {
            asm volatile("cp.async.wait_group 1;");
        } else {
            asm volatile("cp.async.wait_group 0;");
        }
        __syncthreads();

        const unsigned* As = sm + (t % NSTG) * STG;   // half2 units per row: 16
        const unsigned* Bs = As + ASZ;

#pragma unroll
        for (int kk = 0; kk < 16; kk += 8) {     // 2 k-steps of k16 (half2 units)
            unsigned a[4][4], bf[4][2];
#pragma unroll
            for (int mt = 0; mt < 4; mt++) {
                int r = wm * 64 + mt * 16 + g;
                a[mt][0] = As[r * RSTR + kk + tg];
                a[mt][1] = As[(r + 8) * RSTR + kk + tg];
                a[mt][2] = As[r * RSTR + kk + tg + 4];
                a[mt][3] = As[(r + 8) * RSTR + kk + tg + 4];
            }
#pragma unroll
            for (int nt = 0; nt < 4; nt++) {
                int cn = wn * 32 + nt * 8 + g;
                bf[nt][0] = Bs[cn * RSTR + kk + tg];
                bf[nt][1] = Bs[cn * RSTR + kk + tg + 4];
            }
#pragma unroll
            for (int mt = 0; mt < 4; mt++)
#pragma unroll
                for (int nt = 0; nt < 4; nt++)
                    asm volatile(
                        "mma.sync.aligned.m16n8k16.row.col.f32.f16.f16.f32 "
                        "{%0,%1,%2,%3}, {%4,%5,%6,%7}, {%8,%9}, {%0,%1,%2,%3};"
                        : "+f"(acc[mt][nt][0]), "+f"(acc[mt][nt][1]),
                          "+f"(acc[mt][nt][2]), "+f"(acc[mt][nt][3])
                        : "r"(a[mt][0]), "r"(a[mt][1]), "r"(a[mt][2]), "r"(a[mt][3]),
                          "r"(bf[nt][0]), "r"(bf[nt][1]));
        }
        __syncthreads();
    }

#pragma unroll
    for (int mt = 0; mt < 4; mt++) {
        int r = row0 + wm * 64 + mt * 16 + g;
#pragma unroll
        for (int nt = 0; nt < 4; nt++) {
            int cc = col0 + wn * 32 + nt * 8 + 2 * tg;
            *(float2*)&C[(size_t)r * N + cc]       = make_float2(acc[mt][nt][0], acc[mt][nt][1]);
            *(float2*)&C[(size_t)(r + 8) * N + cc] = make_float2(acc[mt][nt][2], acc[mt][nt][3]);
        }
    }
}

// ============================================================================
// Depthwise conv(3) + bias + SiLU over xBC channels (cols 2048..8191 of zxbc)
// ============================================================================
__global__ void conv_silu_kernel(const float* __restrict__ zxbc,
                                 const float* __restrict__ cw,
                                 const float* __restrict__ cb,
                                 float* __restrict__ out)
{
    int ch = blockIdx.x * blockDim.x + threadIdx.x;
    int r  = blockIdx.y;
    if (ch >= CONVD) return;
    int l = r & (SEQ - 1);
    const float* col = zxbc + DMODEL + ch;
    float xm = (l > 0)       ? col[(size_t)(r - 1) * ZXB_LD] : 0.f;
    float x0 =                 col[(size_t)r       * ZXB_LD];
    float xp = (l < SEQ - 1) ? col[(size_t)(r + 1) * ZXB_LD] : 0.f;
    float v = fmaf(cw[ch * 3], xm, fmaf(cw[ch * 3 + 1], x0, fmaf(cw[ch * 3 + 2], xp, cb[ch])));
    out[(size_t)r * CONVD + ch] = v / (1.f + expf(-v));
}

// ============================================================================
// Per-chunk SSD
// ============================================================================
__global__ __launch_bounds__(256) void ssd_chunk_kernel(const float* __restrict__ xbca,
                                                        float* __restrict__ ydiag,
                                                        float* __restrict__ cs)
{
    __shared__ float Bs[64][64];
    __shared__ float Cs[64][64];
    __shared__ float Gs[64][64];

    int bid = blockIdx.x;
    int c  = bid & 63;
    int bh = bid >> 6;
    int h  = bh & 31;
    int b  = bh >> 5;
    size_t row0 = (size_t)(b * SEQ + c * CHUNK) * CONVD;
    int tid = threadIdx.x;

    for (int i = tid; i < 64 * 16; i += 256) {
        int l = i >> 4, q = (i & 15) * 4;
        *(float4*)&Bs[l][q] = *(const float4*)&xbca[row0 + (size_t)l * CONVD + DMODEL + h * 64 + q];
        *(float4*)&Cs[l][q] = *(const float4*)&xbca[row0 + (size_t)l * CONVD + 2 * DMODEL + h * 64 + q];
    }
    __syncthreads();

    int l  = tid >> 2;
    int m0 = tid & 3;
    for (int m = m0; m <= l; m += 4) {
        float a = 0.f;
#pragma unroll 8
        for (int n = 0; n < 64; n++) a += Cs[l][n] * Bs[m][n];
        Gs[l][m] = a;
    }
    __syncthreads();

    for (int i = tid; i < 64 * 16; i += 256) {
        int ll = i >> 4, q = (i & 15) * 4;
        *(float4*)&Cs[ll][q] = *(const float4*)&xbca[row0 + (size_t)ll * CONVD + h * 64 + q];
    }
    __syncthreads();

    for (int p = m0; p < 64; p += 4) {
        float a = 0.f;
        for (int m = 0; m <= l; m++) a += Gs[l][m] * Cs[m][p];
        ydiag[(size_t)(b * SEQ + c * CHUNK + l) * DMODEL + h * 64 + p] = a;
    }

    if (tid < 64) {
        float a = 0.f;
#pragma unroll 8
        for (int ll = 0; ll < 64; ll++) a += Cs[ll][tid] * Bs[ll][tid];
        cs[(size_t)bid * 64 + tid] = a;
    }
}

// ============================================================================
// Inter-chunk scan (constant decay exp(63*A_log[h]) per head)
// ============================================================================
__global__ void scan_kernel(const float* __restrict__ cs, const float* __restrict__ A_log,
                            float* __restrict__ prev)
{
    int bh = blockIdx.x;
    int h  = bh & 31;
    int n  = threadIdx.x;
    float d = expf(63.f * A_log[h]);
    float s = 0.f;
    for (int c = 0; c < NCHUNK; c++) {
        size_t idx = ((size_t)bh * NCHUNK + c) * 64 + n;
        prev[idx] = s;
        s = s * d + cs[idx];
    }
}

// ============================================================================
// Y = Y_diag + Y_off; gate with silu(z); RMSNorm. Output fp16.
// ============================================================================
__global__ __launch_bounds__(256) void combine_kernel(
    const float* __restrict__ ydiag, const float* __restrict__ zxbc,
    const float* __restrict__ xbca,  const float* __restrict__ prev,
    const float* __restrict__ rms_w, __half* __restrict__ yn)
{
    int r = blockIdx.x;
    int b = r >> 12;
    int l = r & (SEQ - 1);
    int c = l >> 6;

    __shared__ float sh_yoff[NHEADS];
    __shared__ float sh_red[8];

    int tid = threadIdx.x, warp = tid >> 5, lane = tid & 31;

    for (int h = warp; h < NHEADS; h += 8) {
        const float* Crow = xbca + (size_t)r * CONVD + 2 * DMODEL + h * 64;
        const float* pv   = prev + ((size_t)(b * NHEADS + h) * NCHUNK + c) * 64;
        int n0 = lane * 2;
        float v = Crow[n0] * pv[n0] + Crow[n0 + 1] * pv[n0 + 1];
#pragma unroll
        for (int o = 16; o; o >>= 1) v += __shfl_down_sync(0xffffffffu, v, o);
        if (lane == 0) sh_yoff[h] = v;
    }
    __syncthreads();

    float vals[8];
    float ss = 0.f;
#pragma unroll
    for (int j = 0; j < 8; j++) {
        int d = tid + j * 256;
        float z  = zxbc[(size_t)r * ZXB_LD + d];
        float sz = z / (1.f + expf(-z));
        float y  = (ydiag[(size_t)r * DMODEL + d] + sh_yoff[d >> 6]) * sz;
        vals[j] = y;
        ss += y * y;
    }
#pragma unroll
    for (int o = 16; o; o >>= 1) ss += __shfl_down_sync(0xffffffffu, ss, o);
    if (lane == 0) sh_red[warp] = ss;
    __syncthreads();
    if (tid == 0) {
        float t = 0.f;
#pragma unroll
        for (int w = 0; w < 8; w++) t += sh_red[w];
        sh_red[0] = rsqrtf(t / (float)DMODEL + RMS_EPS);
    }
    __syncthreads();
    float scale = sh_red[0];
#pragma unroll
    for (int j = 0; j < 8; j++) {
        int d = tid + j * 256;
        yn[(size_t)r * DMODEL + d] = __float2half_rn(vals[j] * scale * rms_w[d]);
    }
}

// ============================================================================
// launch
// ============================================================================
extern "C" void kernel_launch(void* const* d_in, const int* in_sizes, int n_in,
                              void* d_out, int out_size)
{
    const float* u      = (const float*)d_in[0];
    const float* W_in   = (const float*)d_in[1];
    const float* W_out  = (const float*)d_in[2];
    const float* conv_w = (const float*)d_in[3];
    const float* conv_b = (const float*)d_in[4];
    const float* A_log  = (const float*)d_in[5];
    const float* rms_w  = (const float*)d_in[6];
    float* out = (float*)d_out;

    float *zxbc, *xbca, *y, *cs, *prev;
    __half *yn, *ut, *wit, *wot;
    cudaGetSymbolAddress((void**)&zxbc, g_zxbc);
    cudaGetSymbolAddress((void**)&xbca, g_xbca);
    cudaGetSymbolAddress((void**)&y,    g_y);
    cudaGetSymbolAddress((void**)&yn,   g_yn);
    cudaGetSymbolAddress((void**)&cs,   g_cs);
    cudaGetSymbolAddress((void**)&prev, g_prev);
    cudaGetSymbolAddress((void**)&ut,   g_ut);
    cudaGetSymbolAddress((void**)&wit,  g_wit);
    cudaGetSymbolAddress((void**)&wot,  g_wot);

    static bool attr_done = false;
    if (!attr_done) {
        cudaFuncSetAttribute(gemm_tn_f16, cudaFuncAttributeMaxDynamicSharedMemorySize, GSMEM);
        attr_done = true;
    }

    // 0) convert operands to fp16
    {
        size_t n4u = (size_t)ROWS * DMODEL / 4;
        h_convert<<<(unsigned)((n4u + 255) / 256), 256>>>(u, ut, n4u);
        size_t n4w = (size_t)ZXB_LD * DMODEL / 4;
        h_convert<<<(unsigned)((n4w + 255) / 256), 256>>>(W_in, wit, n4w);
        size_t n4o = (size_t)DMODEL * DMODEL / 4;
        h_convert<<<(unsigned)((n4o + 255) / 256), 256>>>(W_out, wot, n4o);
    }
    // 1) zxbc = u @ W_in^T (first 8192 output cols; dt cols unused)
    gemm_tn_f16<<<dim3(ZXB_LD / 128, ROWS / 128), 256, GSMEM>>>(ut, wit, zxbc, ROWS, ZXB_LD, DMODEL);
    // 2) depthwise conv + silu
    conv_silu_kernel<<<dim3(CONVD / 256, ROWS), 256>>>(zxbc, conv_w, conv_b, xbca);
    // 3) per-chunk SSD
    ssd_chunk_kernel<<<BATCH * NHEADS * NCHUNK, 256>>>(xbca, y, cs);
    // 4) inter-chunk scan
    scan_kernel<<<BATCH * NHEADS, 64>>>(cs, A_log, prev);
    // 5) Y_off + gate + rmsnorm (writes fp16)
    combine_kernel<<<ROWS, 256>>>(y, zxbc, xbca, prev, rms_w, yn);
    // 6) out = yn @ W_out^T
    gemm_tn_f16<<<dim3(DMODEL / 128, ROWS / 128), 256, GSMEM>>>(yn, wot, out, ROWS, DMODEL, DMODEL);
}

// round 7
// speedup vs baseline: 1.6330x; 1.1153x over previous
#include <cuda_runtime.h>
#include <cuda_fp16.h>
#include <math.h>
#include <stdint.h>

// ---------------- constants ----------------
#define BATCH   2
#define SEQ     4096
#define ROWS    (BATCH*SEQ)        // 8192
#define DMODEL  2048
#define DSTATE  64
#define DHEAD   64
#define NHEADS  32
#define CHUNK   64
#define NCHUNK  (SEQ/CHUNK)        // 64
#define CONVD   6144
#define ZXB_LD  8192               // cols we compute of zxbcdt (dt cols unused)
#define RMS_EPS 1.1920929e-07f

// ---------------- scratch ----------------
__device__ float  g_zxbc[(size_t)ROWS * ZXB_LD];
__device__ float  g_xbca[(size_t)ROWS * CONVD];
__device__ float  g_y   [(size_t)ROWS * DMODEL];
__device__ __half g_yn  [(size_t)ROWS * DMODEL];
__device__ float  g_cs  [(size_t)BATCH*NHEADS*NCHUNK*DSTATE];
__device__ float  g_prev[(size_t)BATCH*NHEADS*NCHUNK*DSTATE];
__device__ __half g_ut  [(size_t)ROWS * DMODEL];
__device__ __half g_wit [(size_t)ZXB_LD * DMODEL];
__device__ __half g_wot [(size_t)DMODEL * DMODEL];

// ---------------- helpers ----------------
__device__ __forceinline__ void cp16(void* dst, const void* src) {
    unsigned saddr = (unsigned)__cvta_generic_to_shared(dst);
    asm volatile("cp.async.cg.shared.global [%0], [%1], 16;" :: "r"(saddr), "l"(src));
}

__global__ void h_convert(const float* __restrict__ in, __half* __restrict__ out, size_t n4)
{
    size_t i = (size_t)blockIdx.x * blockDim.x + threadIdx.x;
    if (i >= n4) return;
    float4 v = ((const float4*)in)[i];
    __half2 lo = __floats2half2_rn(v.x, v.y);
    __half2 hi = __floats2half2_rn(v.z, v.w);
    uint2 o;
    o.x = *(unsigned*)&lo;
    o.y = *(unsigned*)&hi;
    ((uint2*)out)[i] = o;
}

// ============================================================================
// GEMM: C[M,N] = A[M,K] * B[N,K]^T ; A,B fp16 row-major; fp32 accumulate.
// Block 128x128, K-tile 32 halfs, 8 warps (2m x 4n), warp tile 64x32,
// m16n8k16 grid 4x4, 2 k-steps per tile. 3-stage cp.async ring.
// Fragments via ldmatrix (x4 for A, x2 for B); 80B rows -> conflict-free.
// ============================================================================
#define NSTG  3
#define RSTR  20                    // u32 per smem row (64B data + 16B pad)
#define ASZ   (128 * RSTR)          // u32 per stage per matrix
#define STG   (2 * ASZ)
#define GSMEM (NSTG * STG * 4)      // 61440 B

__global__ __launch_bounds__(256, 2) void gemm_tn_f16(
    const __half* __restrict__ A, const __half* __restrict__ B,
    float* __restrict__ C, int M, int N, int K)
{
    extern __shared__ __align__(16) unsigned sm[];

    const int tid  = threadIdx.x;
    const int row0 = blockIdx.y * 128;
    const int col0 = blockIdx.x * 128;
    const int warp = tid >> 5, lane = tid & 31;
    const int wm = warp >> 2, wn = warp & 3;
    const int g  = lane >> 2, tg = lane & 3;
    (void)g; (void)tg;

    float acc[4][4][4];
#pragma unroll
    for (int i = 0; i < 4; i++)
#pragma unroll
        for (int j = 0; j < 4; j++)
#pragma unroll
            for (int k = 0; k < 4; k++) acc[i][j][k] = 0.f;

    const __half* Ag = A + (size_t)row0 * K;
    const __half* Bg = B + (size_t)col0 * K;
    const int NT = K >> 5;

    auto issue = [&](int j) {
        unsigned* as = sm + (j % NSTG) * STG;
        unsigned* bs = as + ASZ;
        int k0 = j * 32;
#pragma unroll
        for (int i = 0; i < 2; i++) {
            int ch = tid + i * 256;
            int r = ch >> 2, c = ch & 3;
            cp16(&as[r * RSTR + c * 4], Ag + (size_t)r * K + k0 + c * 8);
        }
#pragma unroll
        for (int i = 0; i < 2; i++) {
            int ch = tid + i * 256;
            int r = ch >> 2, c = ch & 3;
            cp16(&bs[r * RSTR + c * 4], Bg + (size_t)r * K + k0 + c * 8);
        }
        asm volatile("cp.async.commit_group;");
    };

    issue(0);
    if (NT > 1) issue(1);

    const unsigned smb = (unsigned)__cvta_generic_to_shared(sm);
    // ldmatrix per-thread address components (byte offsets within a stage)
    const unsigned aoff = ((unsigned)(wm * 64 + (lane & 15)) * RSTR + (lane >> 4) * 4) * 4;
    const unsigned boff = (unsigned)ASZ * 4 +
                          ((unsigned)(wn * 32 + (lane & 7)) * RSTR + ((lane >> 3) & 1) * 4) * 4;

    for (int t = 0; t < NT; t++) {
        if (t + 2 < NT) {
            issue(t + 2);
            asm volatile("cp.async.wait_group 2;");
        } else if (t + 1 < NT) {
            asm volatile("cp.async.wait_group 1;");
        } else {
            asm volatile("cp.async.wait_group 0;");
        }
        __syncthreads();

        const unsigned sb = smb + (unsigned)(t % NSTG) * (STG * 4);
        const unsigned aA = sb + aoff;
        const unsigned aB = sb + boff;

#pragma unroll
        for (int ks = 0; ks < 2; ks++) {         // two k16 steps; byte offset 32*ks
            unsigned a[4][4], bf[4][2];
#pragma unroll
            for (int mt = 0; mt < 4; mt++)
                asm volatile(
                    "ldmatrix.sync.aligned.m8n8.x4.shared.b16 {%0,%1,%2,%3}, [%4];"
                    : "=r"(a[mt][0]), "=r"(a[mt][1]), "=r"(a[mt][2]), "=r"(a[mt][3])
                    : "r"(aA + mt * (16 * RSTR * 4) + ks * 32));
#pragma unroll
            for (int nt = 0; nt < 4; nt++)
                asm volatile(
                    "ldmatrix.sync.aligned.m8n8.x2.shared.b16 {%0,%1}, [%2];"
                    : "=r"(bf[nt][0]), "=r"(bf[nt][1])
                    : "r"(aB + nt * (8 * RSTR * 4) + ks * 32));
#pragma unroll
            for (int mt = 0; mt < 4; mt++)
#pragma unroll
                for (int nt = 0; nt < 4; nt++)
                    asm volatile(
                        "mma.sync.aligned.m16n8k16.row.col.f32.f16.f16.f32 "
                        "{%0,%1,%2,%3}, {%4,%5,%6,%7}, {%8,%9}, {%0,%1,%2,%3};"
                        : "+f"(acc[mt][nt][0]), "+f"(acc[mt][nt][1]),
                          "+f"(acc[mt][nt][2]), "+f"(acc[mt][nt][3])
                        : "r"(a[mt][0]), "r"(a[mt][1]), "r"(a[mt][2]), "r"(a[mt][3]),
                          "r"(bf[nt][0]), "r"(bf[nt][1]));
        }
        __syncthreads();
    }

    const int gg = lane >> 2, tt = lane & 3;
#pragma unroll
    for (int mt = 0; mt < 4; mt++) {
        int r = row0 + wm * 64 + mt * 16 + gg;
#pragma unroll
        for (int nt = 0; nt < 4; nt++) {
            int cc = col0 + wn * 32 + nt * 8 + 2 * tt;
            *(float2*)&C[(size_t)r * N + cc]       = make_float2(acc[mt][nt][0], acc[mt][nt][1]);
            *(float2*)&C[(size_t)(r + 8) * N + cc] = make_float2(acc[mt][nt][2], acc[mt][nt][3]);
        }
    }
}

// ============================================================================
// Depthwise conv(3) + bias + SiLU over xBC channels (cols 2048..8191 of zxbc)
// ============================================================================
__global__ void conv_silu_kernel(const float* __restrict__ zxbc,
                                 const float* __restrict__ cw,
                                 const float* __restrict__ cb,
                                 float* __restrict__ out)
{
    int ch = blockIdx.x * blockDim.x + threadIdx.x;
    int r  = blockIdx.y;
    if (ch >= CONVD) return;
    int l = r & (SEQ - 1);
    const float* col = zxbc + DMODEL + ch;
    float xm = (l > 0)       ? col[(size_t)(r - 1) * ZXB_LD] : 0.f;
    float x0 =                 col[(size_t)r       * ZXB_LD];
    float xp = (l < SEQ - 1) ? col[(size_t)(r + 1) * ZXB_LD] : 0.f;
    float v = fmaf(cw[ch * 3], xm, fmaf(cw[ch * 3 + 1], x0, fmaf(cw[ch * 3 + 2], xp, cb[ch])));
    out[(size_t)r * CONVD + ch] = v / (1.f + expf(-v));
}

// ============================================================================
// Per-chunk SSD, vectorized. Tiles padded to stride 68 (conflict-free float4).
// G upper triangle zero-filled -> uniform 64-iteration Y loop, no divergence.
// Dynamic smem: 3 * 64*68 floats = 52224 B.
// ============================================================================
#define SPAD 68
#define SSD_SMEM (3 * 64 * SPAD * 4)

__global__ __launch_bounds__(256, 2) void ssd_chunk_kernel(const float* __restrict__ xbca,
                                                           float* __restrict__ ydiag,
                                                           float* __restrict__ cs)
{
    extern __shared__ float ssm[];
    float* Bs = ssm;
    float* Cs = ssm + 64 * SPAD;   // C first, then reused for x
    float* Gs = ssm + 2 * 64 * SPAD;

    int bid = blockIdx.x;
    int c  = bid & 63;
    int bh = bid >> 6;
    int h  = bh & 31;
    int b  = bh >> 5;
    size_t row0 = (size_t)(b * SEQ + c * CHUNK) * CONVD;
    int tid = threadIdx.x;

    // load B, C tiles (float4); zero G
    for (int i = tid; i < 64 * 16; i += 256) {
        int l = i >> 4, q = (i & 15) * 4;
        *(float4*)&Bs[l * SPAD + q] = *(const float4*)&xbca[row0 + (size_t)l * CONVD + DMODEL + h * 64 + q];
        *(float4*)&Cs[l * SPAD + q] = *(const float4*)&xbca[row0 + (size_t)l * CONVD + 2 * DMODEL + h * 64 + q];
    }
    for (int i = tid; i < 64 * SPAD; i += 256) Gs[i] = 0.f;
    __syncthreads();

    const int l  = tid >> 2;
    const int m0 = tid & 3;

    // G[l][m] = sum_n C[l][n] * B[m][n], lower triangle only
    for (int m = m0; m <= l; m += 4) {
        float4 s = make_float4(0.f, 0.f, 0.f, 0.f);
#pragma unroll 4
        for (int n = 0; n < 64; n += 4) {
            float4 cv = *(const float4*)&Cs[l * SPAD + n];
            float4 bv = *(const float4*)&Bs[m * SPAD + n];
            s.x = fmaf(cv.x, bv.x, s.x);
            s.y = fmaf(cv.y, bv.y, s.y);
            s.z = fmaf(cv.z, bv.z, s.z);
            s.w = fmaf(cv.w, bv.w, s.w);
        }
        Gs[l * SPAD + m] = (s.x + s.y) + (s.z + s.w);
    }
    __syncthreads();

    // cs[n] = sum_l x[l][n] * B[l][n] -- read x straight from gmem (coalesced)
    // (done before Cs is overwritten below would race; x not yet in smem, so
    //  compute after loading x)
    for (int i = tid; i < 64 * 16; i += 256) {
        int ll = i >> 4, q = (i & 15) * 4;
        *(float4*)&Cs[ll * SPAD + q] = *(const float4*)&xbca[row0 + (size_t)ll * CONVD + h * 64 + q];
    }
    __syncthreads();

    // Y[l][p] = sum_m G[l][m] * x[m][p] ; uniform 64-m loop (G upper = 0)
    {
        const int q = m0;               // p block = q*16
        float4 acc0 = make_float4(0.f,0.f,0.f,0.f);
        float4 acc1 = acc0, acc2 = acc0, acc3 = acc0;
        const float* gr = &Gs[l * SPAD];
#pragma unroll 4
        for (int m = 0; m < 64; m++) {
            float gv = gr[m];
            const float* xr = &Cs[m * SPAD + q * 16];
            float4 x0 = *(const float4*)&xr[0];
            float4 x1 = *(const float4*)&xr[4];
            float4 x2 = *(const float4*)&xr[8];
            float4 x3 = *(const float4*)&xr[12];
            acc0.x = fmaf(gv, x0.x, acc0.x); acc0.y = fmaf(gv, x0.y, acc0.y);
            acc0.z = fmaf(gv, x0.z, acc0.z); acc0.w = fmaf(gv, x0.w, acc0.w);
            acc1.x = fmaf(gv, x1.x, acc1.x); acc1.y = fmaf(gv, x1.y, acc1.y);
            acc1.z = fmaf(gv, x1.z, acc1.z); acc1.w = fmaf(gv, x1.w, acc1.w);
            acc2.x = fmaf(gv, x2.x, acc2.x); acc2.y = fmaf(gv, x2.y, acc2.y);
            acc2.z = fmaf(gv, x2.z, acc2.z); acc2.w = fmaf(gv, x2.w, acc2.w);
            acc3.x = fmaf(gv, x3.x, acc3.x); acc3.y = fmaf(gv, x3.y, acc3.y);
            acc3.z = fmaf(gv, x3.z, acc3.z); acc3.w = fmaf(gv, x3.w, acc3.w);
        }
        float* yr = &ydiag[(size_t)(b * SEQ + c * CHUNK + l) * DMODEL + h * 64 + q * 16];
        *(float4*)&yr[0]  = acc0;
        *(float4*)&yr[4]  = acc1;
        *(float4*)&yr[8]  = acc2;
        *(float4*)&yr[12] = acc3;
    }

    // chunk state
    if (tid < 64) {
        float a = 0.f;
#pragma unroll 8
        for (int ll = 0; ll < 64; ll++)
            a = fmaf(Cs[ll * SPAD + tid], Bs[ll * SPAD + tid], a);
        cs[(size_t)bid * 64 + tid] = a;
    }
}

// ============================================================================
// Inter-chunk scan (constant decay exp(63*A_log[h]) per head)
// ============================================================================
__global__ void scan_kernel(const float* __restrict__ cs, const float* __restrict__ A_log,
                            float* __restrict__ prev)
{
    int bh = blockIdx.x;
    int h  = bh & 31;
    int n  = threadIdx.x;
    float d = expf(63.f * A_log[h]);
    float s = 0.f;
    for (int c = 0; c < NCHUNK; c++) {
        size_t idx = ((size_t)bh * NCHUNK + c) * 64 + n;
        prev[idx] = s;
        s = s * d + cs[idx];
    }
}

// ============================================================================
// Y = Y_diag + Y_off; gate with silu(z); RMSNorm. Output fp16.
// ============================================================================
__global__ __launch_bounds__(256) void combine_kernel(
    const float* __restrict__ ydiag, const float* __restrict__ zxbc,
    const float* __restrict__ xbca,  const float* __restrict__ prev,
    const float* __restrict__ rms_w, __half* __restrict__ yn)
{
    int r = blockIdx.x;
    int b = r >> 12;
    int l = r & (SEQ - 1);
    int c = l >> 6;

    __shared__ float sh_yoff[NHEADS];
    __shared__ float sh_red[8];

    int tid = threadIdx.x, warp = tid >> 5, lane = tid & 31;

    for (int h = warp; h < NHEADS; h += 8) {
        const float* Crow = xbca + (size_t)r * CONVD + 2 * DMODEL + h * 64;
        const float* pv   = prev + ((size_t)(b * NHEADS + h) * NCHUNK + c) * 64;
        int n0 = lane * 2;
        float v = Crow[n0] * pv[n0] + Crow[n0 + 1] * pv[n0 + 1];
#pragma unroll
        for (int o = 16; o; o >>= 1) v += __shfl_down_sync(0xffffffffu, v, o);
        if (lane == 0) sh_yoff[h] = v;
    }
    __syncthreads();

    float vals[8];
    float ss = 0.f;
#pragma unroll
    for (int j = 0; j < 8; j++) {
        int d = tid + j * 256;
        float z  = zxbc[(size_t)r * ZXB_LD + d];
        float sz = z / (1.f + expf(-z));
        float y  = (ydiag[(size_t)r * DMODEL + d] + sh_yoff[d >> 6]) * sz;
        vals[j] = y;
        ss += y * y;
    }
#pragma unroll
    for (int o = 16; o; o >>= 1) ss += __shfl_down_sync(0xffffffffu, ss, o);
    if (lane == 0) sh_red[warp] = ss;
    __syncthreads();
    if (tid == 0) {
        float t = 0.f;
#pragma unroll
        for (int w = 0; w < 8; w++) t += sh_red[w];
        sh_red[0] = rsqrtf(t / (float)DMODEL + RMS_EPS);
    }
    __syncthreads();
    float scale = sh_red[0];
#pragma unroll
    for (int j = 0; j < 8; j++) {
        int d = tid + j * 256;
        yn[(size_t)r * DMODEL + d] = __float2half_rn(vals[j] * scale * rms_w[d]);
    }
}

// ============================================================================
// launch
// ============================================================================
extern "C" void kernel_launch(void* const* d_in, const int* in_sizes, int n_in,
                              void* d_out, int out_size)
{
    const float* u      = (const float*)d_in[0];
    const float* W_in   = (const float*)d_in[1];
    const float* W_out  = (const float*)d_in[2];
    const float* conv_w = (const float*)d_in[3];
    const float* conv_b = (const float*)d_in[4];
    const float* A_log  = (const float*)d_in[5];
    const float* rms_w  = (const float*)d_in[6];
    float* out = (float*)d_out;

    float *zxbc, *xbca, *y, *cs, *prev;
    __half *yn, *ut, *wit, *wot;
    cudaGetSymbolAddress((void**)&zxbc, g_zxbc);
    cudaGetSymbolAddress((void**)&xbca, g_xbca);
    cudaGetSymbolAddress((void**)&y,    g_y);
    cudaGetSymbolAddress((void**)&yn,   g_yn);
    cudaGetSymbolAddress((void**)&cs,   g_cs);
    cudaGetSymbolAddress((void**)&prev, g_prev);
    cudaGetSymbolAddress((void**)&ut,   g_ut);
    cudaGetSymbolAddress((void**)&wit,  g_wit);
    cudaGetSymbolAddress((void**)&wot,  g_wot);

    static bool attr_done = false;
    if (!attr_done) {
        cudaFuncSetAttribute(gemm_tn_f16, cudaFuncAttributeMaxDynamicSharedMemorySize, GSMEM);
        cudaFuncSetAttribute(ssd_chunk_kernel, cudaFuncAttributeMaxDynamicSharedMemorySize, SSD_SMEM);
        attr_done = true;
    }

    // 0) convert operands to fp16
    {
        size_t n4u = (size_t)ROWS * DMODEL / 4;
        h_convert<<<(unsigned)((n4u + 255) / 256), 256>>>(u, ut, n4u);
        size_t n4w = (size_t)ZXB_LD * DMODEL / 4;
        h_convert<<<(unsigned)((n4w + 255) / 256), 256>>>(W_in, wit, n4w);
        size_t n4o = (size_t)DMODEL * DMODEL / 4;
        h_convert<<<(unsigned)((n4o + 255) / 256), 256>>>(W_out, wot, n4o);
    }
    // 1) zxbc = u @ W_in^T (first 8192 output cols; dt cols unused)
    gemm_tn_f16<<<dim3(ZXB_LD / 128, ROWS / 128), 256, GSMEM>>>(ut, wit, zxbc, ROWS, ZXB_LD, DMODEL);
    // 2) depthwise conv + silu
    conv_silu_kernel<<<dim3(CONVD / 256, ROWS), 256>>>(zxbc, conv_w, conv_b, xbca);
    // 3) per-chunk SSD
    ssd_chunk_kernel<<<BATCH * NHEADS * NCHUNK, 256, SSD_SMEM>>>(xbca, y, cs);
    // 4) inter-chunk scan
    scan_kernel<<<BATCH * NHEADS, 64>>>(cs, A_log, prev);
    // 5) Y_off + gate + rmsnorm (writes fp16)
    combine_kernel<<<ROWS, 256>>>(y, zxbc, xbca, prev, rms_w, yn);
    // 6) out = yn @ W_out^T
    gemm_tn_f16<<<dim3(DMODEL / 128, ROWS / 128), 256, GSMEM>>>(yn, wot, out, ROWS, DMODEL, DMODEL);
}

// round 8
// speedup vs baseline: 2.0776x; 1.2722x over previous
#include <cuda_runtime.h>
#include <cuda_fp16.h>
#include <math.h>
#include <stdint.h>

// ---------------- constants ----------------
#define BATCH   2
#define SEQ     4096
#define ROWS    (BATCH*SEQ)        // 8192
#define DMODEL  2048
#define DSTATE  64
#define DHEAD   64
#define NHEADS  32
#define CHUNK   64
#define NCHUNK  (SEQ/CHUNK)        // 64
#define CONVD   6144
#define ZXB_LD  8192               // cols we compute of zxbcdt (dt cols unused)
#define RMS_EPS 1.1920929e-07f

// ---------------- scratch ----------------
__device__ float  g_zxbc[(size_t)ROWS * ZXB_LD];
__device__ float  g_xbca[(size_t)ROWS * CONVD];
__device__ float  g_y   [(size_t)ROWS * DMODEL];
__device__ __half g_yn  [(size_t)ROWS * DMODEL];
__device__ float  g_cs  [(size_t)BATCH*NHEADS*NCHUNK*DSTATE];
__device__ float  g_prev[(size_t)BATCH*NHEADS*NCHUNK*DSTATE];
__device__ __half g_ut  [(size_t)ROWS * DMODEL];
__device__ __half g_wit [(size_t)ZXB_LD * DMODEL];
__device__ __half g_wot [(size_t)DMODEL * DMODEL];

// ---------------- helpers ----------------
__device__ __forceinline__ void cp16(void* dst, const void* src) {
    unsigned saddr = (unsigned)__cvta_generic_to_shared(dst);
    asm volatile("cp.async.cg.shared.global [%0], [%1], 16;" :: "r"(saddr), "l"(src));
}

__global__ void h_convert(const float* __restrict__ in, __half* __restrict__ out, size_t n4)
{
    size_t i = (size_t)blockIdx.x * blockDim.x + threadIdx.x;
    if (i >= n4) return;
    float4 v = ((const float4*)in)[i];
    __half2 lo = __floats2half2_rn(v.x, v.y);
    __half2 hi = __floats2half2_rn(v.z, v.w);
    uint2 o;
    o.x = *(unsigned*)&lo;
    o.y = *(unsigned*)&hi;
    ((uint2*)out)[i] = o;
}

// ============================================================================
// GEMM: C[M,N] = A[M,K] * B[N,K]^T ; A,B fp16 row-major; fp32 accumulate.
// Block 128x128, K-tile 64 halfs (128B rows, SW128 XOR swizzle), 8 warps
// (2m x 4n), warp tile 64x32, m16n8k16, 4 k-steps per tile (128 MMAs/warp
// between sync pairs). 3-stage cp.async ring, 96KB smem -> 2 CTAs/SM.
// ============================================================================
#define NSTG  3
#define KT    64
#define ASZ   (128 * 32)            // u32 per stage per matrix (128 rows x 128B)
#define STG   (2 * ASZ)             // 8192 u32 = 32KB per stage
#define GSMEM (NSTG * STG * 4)      // 98304 B

__global__ __launch_bounds__(256, 2) void gemm_tn_f16(
    const __half* __restrict__ A, const __half* __restrict__ B,
    float* __restrict__ C, int M, int N, int K)
{
    extern __shared__ __align__(16) unsigned sm[];

    const int tid  = threadIdx.x;
    const int row0 = blockIdx.y * 128;
    const int col0 = blockIdx.x * 128;
    const int warp = tid >> 5, lane = tid & 31;
    const int wm = warp >> 2, wn = warp & 3;

    float acc[4][4][4];
#pragma unroll
    for (int i = 0; i < 4; i++)
#pragma unroll
        for (int j = 0; j < 4; j++)
#pragma unroll
            for (int k = 0; k < 4; k++) acc[i][j][k] = 0.f;

    const __half* Ag = A + (size_t)row0 * K;
    const __half* Bg = B + (size_t)col0 * K;
    const int NT = K / KT;

    // fill stage j%NSTG with K-tile j: 128 rows x 8 16B-chunks per matrix,
    // chunk c of row r stored at (c ^ (r&7)) -- SW128 swizzle.
    auto issue = [&](int j) {
        unsigned* as = sm + (j % NSTG) * STG;
        unsigned* bs = as + ASZ;
        int k0 = j * KT;
#pragma unroll
        for (int i = 0; i < 4; i++) {
            int ch = tid + i * 256;            // 0..1023
            int r = ch >> 3, c = ch & 7;
            cp16(&as[r * 32 + ((c ^ (r & 7)) << 2)], Ag + (size_t)r * K + k0 + c * 8);
        }
#pragma unroll
        for (int i = 0; i < 4; i++) {
            int ch = tid + i * 256;
            int r = ch >> 3, c = ch & 7;
            cp16(&bs[r * 32 + ((c ^ (r & 7)) << 2)], Bg + (size_t)r * K + k0 + c * 8);
        }
        asm volatile("cp.async.commit_group;");
    };

    issue(0);
    if (NT > 1) issue(1);

    const unsigned smb = (unsigned)__cvta_generic_to_shared(sm);
    // per-thread ldmatrix row/selector components
    const int arow = wm * 64 + (lane & 15);    // + mt*16
    const int acs  = lane >> 4;                // chunk selector 0/1
    const int brow = wn * 32 + (lane & 7);     // + nt*8
    const int bcs  = (lane >> 3) & 1;

    for (int t = 0; t < NT; t++) {
        if (t + 1 < NT) {
            asm volatile("cp.async.wait_group 1;");
        } else {
            asm volatile("cp.async.wait_group 0;");
        }
        __syncthreads();

        const unsigned sb = smb + (unsigned)(t % NSTG) * (STG * 4);

#pragma unroll
        for (int ks = 0; ks < 4; ks++) {       // four k16 steps
            unsigned a[4][4], bf[4][2];
#pragma unroll
            for (int mt = 0; mt < 4; mt++) {
                int r = arow + mt * 16;
                unsigned ad = sb + (unsigned)(r * 128 + (((2 * ks + acs) ^ (r & 7)) << 4));
                asm volatile(
                    "ldmatrix.sync.aligned.m8n8.x4.shared.b16 {%0,%1,%2,%3}, [%4];"
                    : "=r"(a[mt][0]), "=r"(a[mt][1]), "=r"(a[mt][2]), "=r"(a[mt][3])
                    : "r"(ad));
            }
#pragma unroll
            for (int nt = 0; nt < 4; nt++) {
                int r = brow + nt * 8;
                unsigned bd = sb + (unsigned)(ASZ * 4) +
                              (unsigned)(r * 128 + (((2 * ks + bcs) ^ (r & 7)) << 4));
                asm volatile(
                    "ldmatrix.sync.aligned.m8n8.x2.shared.b16 {%0,%1}, [%2];"
                    : "=r"(bf[nt][0]), "=r"(bf[nt][1])
                    : "r"(bd));
            }
#pragma unroll
            for (int mt = 0; mt < 4; mt++)
#pragma unroll
                for (int nt = 0; nt < 4; nt++)
                    asm volatile(
                        "mma.sync.aligned.m16n8k16.row.col.f32.f16.f16.f32 "
                        "{%0,%1,%2,%3}, {%4,%5,%6,%7}, {%8,%9}, {%0,%1,%2,%3};"
                        : "+f"(acc[mt][nt][0]), "+f"(acc[mt][nt][1]),
                          "+f"(acc[mt][nt][2]), "+f"(acc[mt][nt][3])
                        : "r"(a[mt][0]), "r"(a[mt][1]), "r"(a[mt][2]), "r"(a[mt][3]),
                          "r"(bf[nt][0]), "r"(bf[nt][1]));
        }
        __syncthreads();
        if (t + 2 < NT) issue(t + 2);
    }

    const int gg = lane >> 2, tt = lane & 3;
#pragma unroll
    for (int mt = 0; mt < 4; mt++) {
        int r = row0 + wm * 64 + mt * 16 + gg;
#pragma unroll
        for (int nt = 0; nt < 4; nt++) {
            int cc = col0 + wn * 32 + nt * 8 + 2 * tt;
            *(float2*)&C[(size_t)r * N + cc]       = make_float2(acc[mt][nt][0], acc[mt][nt][1]);
            *(float2*)&C[(size_t)(r + 8) * N + cc] = make_float2(acc[mt][nt][2], acc[mt][nt][3]);
        }
    }
}

// ============================================================================
// Depthwise conv(3) + bias + SiLU over xBC channels (cols 2048..8191 of zxbc)
// ============================================================================
__global__ void conv_silu_kernel(const float* __restrict__ zxbc,
                                 const float* __restrict__ cw,
                                 const float* __restrict__ cb,
                                 float* __restrict__ out)
{
    int ch = blockIdx.x * blockDim.x + threadIdx.x;
    int r  = blockIdx.y;
    if (ch >= CONVD) return;
    int l = r & (SEQ - 1);
    const float* col = zxbc + DMODEL + ch;
    float xm = (l > 0)       ? col[(size_t)(r - 1) * ZXB_LD] : 0.f;
    float x0 =                 col[(size_t)r       * ZXB_LD];
    float xp = (l < SEQ - 1) ? col[(size_t)(r + 1) * ZXB_LD] : 0.f;
    float v = fmaf(cw[ch * 3], xm, fmaf(cw[ch * 3 + 1], x0, fmaf(cw[ch * 3 + 2], xp, cb[ch])));
    out[(size_t)r * CONVD + ch] = v / (1.f + expf(-v));
}

// ============================================================================
// Per-chunk SSD, vectorized. Tiles padded to stride 68 (conflict-free float4).
// ============================================================================
#define SPAD 68
#define SSD_SMEM (3 * 64 * SPAD * 4)

__global__ __launch_bounds__(256, 2) void ssd_chunk_kernel(const float* __restrict__ xbca,
                                                           float* __restrict__ ydiag,
                                                           float* __restrict__ cs)
{
    extern __shared__ float ssm[];
    float* Bs = ssm;
    float* Cs = ssm + 64 * SPAD;
    float* Gs = ssm + 2 * 64 * SPAD;

    int bid = blockIdx.x;
    int c  = bid & 63;
    int bh = bid >> 6;
    int h  = bh & 31;
    int b  = bh >> 5;
    size_t row0 = (size_t)(b * SEQ + c * CHUNK) * CONVD;
    int tid = threadIdx.x;

    for (int i = tid; i < 64 * 16; i += 256) {
        int l = i >> 4, q = (i & 15) * 4;
        *(float4*)&Bs[l * SPAD + q] = *(const float4*)&xbca[row0 + (size_t)l * CONVD + DMODEL + h * 64 + q];
        *(float4*)&Cs[l * SPAD + q] = *(const float4*)&xbca[row0 + (size_t)l * CONVD + 2 * DMODEL + h * 64 + q];
    }
    for (int i = tid; i < 64 * SPAD; i += 256) Gs[i] = 0.f;
    __syncthreads();

    const int l  = tid >> 2;
    const int m0 = tid & 3;

    for (int m = m0; m <= l; m += 4) {
        float4 s = make_float4(0.f, 0.f, 0.f, 0.f);
#pragma unroll 4
        for (int n = 0; n < 64; n += 4) {
            float4 cv = *(const float4*)&Cs[l * SPAD + n];
            float4 bv = *(const float4*)&Bs[m * SPAD + n];
            s.x = fmaf(cv.x, bv.x, s.x);
            s.y = fmaf(cv.y, bv.y, s.y);
            s.z = fmaf(cv.z, bv.z, s.z);
            s.w = fmaf(cv.w, bv.w, s.w);
        }
        Gs[l * SPAD + m] = (s.x + s.y) + (s.z + s.w);
    }
    __syncthreads();

    for (int i = tid; i < 64 * 16; i += 256) {
        int ll = i >> 4, q = (i & 15) * 4;
        *(float4*)&Cs[ll * SPAD + q] = *(const float4*)&xbca[row0 + (size_t)ll * CONVD + h * 64 + q];
    }
    __syncthreads();

    {
        const int q = m0;
        float4 acc0 = make_float4(0.f,0.f,0.f,0.f);
        float4 acc1 = acc0, acc2 = acc0, acc3 = acc0;
        const float* gr = &Gs[l * SPAD];
#pragma unroll 4
        for (int m = 0; m < 64; m++) {
            float gv = gr[m];
            const float* xr = &Cs[m * SPAD + q * 16];
            float4 x0 = *(const float4*)&xr[0];
            float4 x1 = *(const float4*)&xr[4];
            float4 x2 = *(const float4*)&xr[8];
            float4 x3 = *(const float4*)&xr[12];
            acc0.x = fmaf(gv, x0.x, acc0.x); acc0.y = fmaf(gv, x0.y, acc0.y);
            acc0.z = fmaf(gv, x0.z, acc0.z); acc0.w = fmaf(gv, x0.w, acc0.w);
            acc1.x = fmaf(gv, x1.x, acc1.x); acc1.y = fmaf(gv, x1.y, acc1.y);
            acc1.z = fmaf(gv, x1.z, acc1.z); acc1.w = fmaf(gv, x1.w, acc1.w);
            acc2.x = fmaf(gv, x2.x, acc2.x); acc2.y = fmaf(gv, x2.y, acc2.y);
            acc2.z = fmaf(gv, x2.z, acc2.z); acc2.w = fmaf(gv, x2.w, acc2.w);
            acc3.x = fmaf(gv, x3.x, acc3.x); acc3.y = fmaf(gv, x3.y, acc3.y);
            acc3.z = fmaf(gv, x3.z, acc3.z); acc3.w = fmaf(gv, x3.w, acc3.w);
        }
        float* yr = &ydiag[(size_t)(b * SEQ + c * CHUNK + l) * DMODEL + h * 64 + q * 16];
        *(float4*)&yr[0]  = acc0;
        *(float4*)&yr[4]  = acc1;
        *(float4*)&yr[8]  = acc2;
        *(float4*)&yr[12] = acc3;
    }

    if (tid < 64) {
        float a = 0.f;
#pragma unroll 8
        for (int ll = 0; ll < 64; ll++)
            a = fmaf(Cs[ll * SPAD + tid], Bs[ll * SPAD + tid], a);
        cs[(size_t)bid * 64 + tid] = a;
    }
}

// ============================================================================
// Inter-chunk scan (constant decay exp(63*A_log[h]) per head)
// ============================================================================
__global__ void scan_kernel(const float* __restrict__ cs, const float* __restrict__ A_log,
                            float* __restrict__ prev)
{
    int bh = blockIdx.x;
    int h  = bh & 31;
    int n  = threadIdx.x;
    float d = expf(63.f * A_log[h]);
    float s = 0.f;
    for (int c = 0; c < NCHUNK; c++) {
        size_t idx = ((size_t)bh * NCHUNK + c) * 64 + n;
        prev[idx] = s;
        s = s * d + cs[idx];
    }
}

// ============================================================================
// Y = Y_diag + Y_off; gate with silu(z); RMSNorm. Output fp16.
// ============================================================================
__global__ __launch_bounds__(256) void combine_kernel(
    const float* __restrict__ ydiag, const float* __restrict__ zxbc,
    const float* __restrict__ xbca,  const float* __restrict__ prev,
    const float* __restrict__ rms_w, __half* __restrict__ yn)
{
    int r = blockIdx.x;
    int b = r >> 12;
    int l = r & (SEQ - 1);
    int c = l >> 6;

    __shared__ float sh_yoff[NHEADS];
    __shared__ float sh_red[8];

    int tid = threadIdx.x, warp = tid >> 5, lane = tid & 31;

    for (int h = warp; h < NHEADS; h += 8) {
        const float* Crow = xbca + (size_t)r * CONVD + 2 * DMODEL + h * 64;
        const float* pv   = prev + ((size_t)(b * NHEADS + h) * NCHUNK + c) * 64;
        int n0 = lane * 2;
        float v = Crow[n0] * pv[n0] + Crow[n0 + 1] * pv[n0 + 1];
#pragma unroll
        for (int o = 16; o; o >>= 1) v += __shfl_down_sync(0xffffffffu, v, o);
        if (lane == 0) sh_yoff[h] = v;
    }
    __syncthreads();

    float vals[8];
    float ss = 0.f;
#pragma unroll
    for (int j = 0; j < 8; j++) {
        int d = tid + j * 256;
        float z  = zxbc[(size_t)r * ZXB_LD + d];
        float sz = z / (1.f + expf(-z));
        float y  = (ydiag[(size_t)r * DMODEL + d] + sh_yoff[d >> 6]) * sz;
        vals[j] = y;
        ss += y * y;
    }
#pragma unroll
    for (int o = 16; o; o >>= 1) ss += __shfl_down_sync(0xffffffffu, ss, o);
    if (lane == 0) sh_red[warp] = ss;
    __syncthreads();
    if (tid == 0) {
        float t = 0.f;
#pragma unroll
        for (int w = 0; w < 8; w++) t += sh_red[w];
        sh_red[0] = rsqrtf(t / (float)DMODEL + RMS_EPS);
    }
    __syncthreads();
    float scale = sh_red[0];
#pragma unroll
    for (int j = 0; j < 8; j++) {
        int d = tid + j * 256;
        yn[(size_t)r * DMODEL + d] = __float2half_rn(vals[j] * scale * rms_w[d]);
    }
}

// ============================================================================
// launch
// ============================================================================
extern "C" void kernel_launch(void* const* d_in, const int* in_sizes, int n_in,
                              void* d_out, int out_size)
{
    const float* u      = (const float*)d_in[0];
    const float* W_in   = (const float*)d_in[1];
    const float* W_out  = (const float*)d_in[2];
    const float* conv_w = (const float*)d_in[3];
    const float* conv_b = (const float*)d_in[4];
    const float* A_log  = (const float*)d_in[5];
    const float* rms_w  = (const float*)d_in[6];
    float* out = (float*)d_out;

    float *zxbc, *xbca, *y, *cs, *prev;
    __half *yn, *ut, *wit, *wot;
    cudaGetSymbolAddress((void**)&zxbc, g_zxbc);
    cudaGetSymbolAddress((void**)&xbca, g_xbca);
    cudaGetSymbolAddress((void**)&y,    g_y);
    cudaGetSymbolAddress((void**)&yn,   g_yn);
    cudaGetSymbolAddress((void**)&cs,   g_cs);
    cudaGetSymbolAddress((void**)&prev, g_prev);
    cudaGetSymbolAddress((void**)&ut,   g_ut);
    cudaGetSymbolAddress((void**)&wit,  g_wit);
    cudaGetSymbolAddress((void**)&wot,  g_wot);

    static bool attr_done = false;
    if (!attr_done) {
        cudaFuncSetAttribute(gemm_tn_f16, cudaFuncAttributeMaxDynamicSharedMemorySize, GSMEM);
        cudaFuncSetAttribute(ssd_chunk_kernel, cudaFuncAttributeMaxDynamicSharedMemorySize, SSD_SMEM);
        attr_done = true;
    }

    // 0) convert operands to fp16
    {
        size_t n4u = (size_t)ROWS * DMODEL / 4;
        h_convert<<<(unsigned)((n4u + 255) / 256), 256>>>(u, ut, n4u);
        size_t n4w = (size_t)ZXB_LD * DMODEL / 4;
        h_convert<<<(unsigned)((n4w + 255) / 256), 256>>>(W_in, wit, n4w);
        size_t n4o = (size_t)DMODEL * DMODEL / 4;
        h_convert<<<(unsigned)((n4o + 255) / 256), 256>>>(W_out, wot, n4o);
    }
    // 1) zxbc = u @ W_in^T (first 8192 output cols; dt cols unused)
    gemm_tn_f16<<<dim3(ZXB_LD / 128, ROWS / 128), 256, GSMEM>>>(ut, wit, zxbc, ROWS, ZXB_LD, DMODEL);
    // 2) depthwise conv + silu
    conv_silu_kernel<<<dim3(CONVD / 256, ROWS), 256>>>(zxbc, conv_w, conv_b, xbca);
    // 3) per-chunk SSD
    ssd_chunk_kernel<<<BATCH * NHEADS * NCHUNK, 256, SSD_SMEM>>>(xbca, y, cs);
    // 4) inter-chunk scan
    scan_kernel<<<BATCH * NHEADS, 64>>>(cs, A_log, prev);
    // 5) Y_off + gate + rmsnorm (writes fp16)
    combine_kernel<<<ROWS, 256>>>(y, zxbc, xbca, prev, rms_w, yn);
    // 6) out = yn @ W_out^T
    gemm_tn_f16<<<dim3(DMODEL / 128, ROWS / 128), 256, GSMEM>>>(yn, wot, out, ROWS, DMODEL, DMODEL);
}

// round 9
// speedup vs baseline: 2.4077x; 1.1589x over previous
#include <cuda_runtime.h>
#include <cuda_fp16.h>
#include <math.h>
#include <stdint.h>

// ---------------- constants ----------------
#define BATCH   2
#define SEQ     4096
#define ROWS    (BATCH*SEQ)        // 8192
#define DMODEL  2048
#define DSTATE  64
#define DHEAD   64
#define NHEADS  32
#define CHUNK   64
#define NCHUNK  (SEQ/CHUNK)        // 64
#define CONVD   6144
#define ZXB_LD  8192               // cols we compute of zxbcdt (dt cols unused)
#define RMS_EPS 1.1920929e-07f

// ---------------- scratch ----------------
__device__ float  g_zxbc[(size_t)ROWS * ZXB_LD];
__device__ float  g_xbca[(size_t)ROWS * CONVD];
__device__ float  g_y   [(size_t)ROWS * DMODEL];
__device__ __half g_yn  [(size_t)ROWS * DMODEL];
__device__ float  g_cs  [(size_t)BATCH*NHEADS*NCHUNK*DSTATE];
__device__ float  g_prev[(size_t)BATCH*NHEADS*NCHUNK*DSTATE];
__device__ __half g_ut  [(size_t)ROWS * DMODEL];
__device__ __half g_wit [(size_t)ZXB_LD * DMODEL];
__device__ __half g_wot [(size_t)DMODEL * DMODEL];

// ---------------- helpers ----------------
__device__ __forceinline__ void cp16(void* dst, const void* src) {
    unsigned saddr = (unsigned)__cvta_generic_to_shared(dst);
    asm volatile("cp.async.cg.shared.global [%0], [%1], 16;" :: "r"(saddr), "l"(src));
}

__global__ void h_convert(const float* __restrict__ in, __half* __restrict__ out, size_t n4)
{
    size_t i = (size_t)blockIdx.x * blockDim.x + threadIdx.x;
    if (i >= n4) return;
    float4 v = ((const float4*)in)[i];
    __half2 lo = __floats2half2_rn(v.x, v.y);
    __half2 hi = __floats2half2_rn(v.z, v.w);
    uint2 o;
    o.x = *(unsigned*)&lo;
    o.y = *(unsigned*)&hi;
    ((uint2*)out)[i] = o;
}

// ============================================================================
// GEMM: C[M,N] = A[M,K] * B[N,K]^T ; A,B fp16 row-major; fp32 accumulate.
// Block 128x128, K-tile 64 halfs (128B rows, SW128 XOR swizzle), 8 warps
// (2m x 4n), warp tile 64x32, m16n8k16. 3-stage cp.async ring, ONE
// __syncthreads per K-tile; cp.async issue overlaps MMA compute.
// ============================================================================
#define NSTG  3
#define KT    64
#define ASZ   (128 * 32)            // u32 per stage per matrix (128 rows x 128B)
#define STG   (2 * ASZ)             // 8192 u32 = 32KB per stage
#define GSMEM (NSTG * STG * 4)      // 98304 B

__global__ __launch_bounds__(256, 2) void gemm_tn_f16(
    const __half* __restrict__ A, const __half* __restrict__ B,
    float* __restrict__ C, int M, int N, int K)
{
    extern __shared__ __align__(16) unsigned sm[];

    const int tid  = threadIdx.x;
    const int row0 = blockIdx.y * 128;
    const int col0 = blockIdx.x * 128;
    const int warp = tid >> 5, lane = tid & 31;
    const int wm = warp >> 2, wn = warp & 3;

    float acc[4][4][4];
#pragma unroll
    for (int i = 0; i < 4; i++)
#pragma unroll
        for (int j = 0; j < 4; j++)
#pragma unroll
            for (int k = 0; k < 4; k++) acc[i][j][k] = 0.f;

    const __half* Ag = A + (size_t)row0 * K;
    const __half* Bg = B + (size_t)col0 * K;
    const int NT = K / KT;

    auto issue = [&](int j) {
        unsigned* as = sm + (j % NSTG) * STG;
        unsigned* bs = as + ASZ;
        int k0 = j * KT;
#pragma unroll
        for (int i = 0; i < 4; i++) {
            int ch = tid + i * 256;            // 0..1023
            int r = ch >> 3, c = ch & 7;
            cp16(&as[r * 32 + ((c ^ (r & 7)) << 2)], Ag + (size_t)r * K + k0 + c * 8);
        }
#pragma unroll
        for (int i = 0; i < 4; i++) {
            int ch = tid + i * 256;
            int r = ch >> 3, c = ch & 7;
            cp16(&bs[r * 32 + ((c ^ (r & 7)) << 2)], Bg + (size_t)r * K + k0 + c * 8);
        }
        asm volatile("cp.async.commit_group;");
    };

    issue(0);
    if (NT > 1) issue(1);

    const unsigned smb = (unsigned)__cvta_generic_to_shared(sm);
    const int arow = wm * 64 + (lane & 15);    // + mt*16
    const int acs  = lane >> 4;
    const int brow = wn * 32 + (lane & 7);     // + nt*8
    const int bcs  = (lane >> 3) & 1;

    for (int t = 0; t < NT; t++) {
        if (t + 1 < NT) {
            asm volatile("cp.async.wait_group 1;");
        } else {
            asm volatile("cp.async.wait_group 0;");
        }
        __syncthreads();
        // stage (t+2)%3 == stage (t-1)%3 was fully consumed before this sync
        if (t + 2 < NT) issue(t + 2);

        const unsigned sb = smb + (unsigned)(t % NSTG) * (STG * 4);

#pragma unroll
        for (int ks = 0; ks < 4; ks++) {
            unsigned a[4][4], bf[4][2];
#pragma unroll
            for (int mt = 0; mt < 4; mt++) {
                int r = arow + mt * 16;
                unsigned ad = sb + (unsigned)(r * 128 + (((2 * ks + acs) ^ (r & 7)) << 4));
                asm volatile(
                    "ldmatrix.sync.aligned.m8n8.x4.shared.b16 {%0,%1,%2,%3}, [%4];"
                    : "=r"(a[mt][0]), "=r"(a[mt][1]), "=r"(a[mt][2]), "=r"(a[mt][3])
                    : "r"(ad));
            }
#pragma unroll
            for (int nt = 0; nt < 4; nt++) {
                int r = brow + nt * 8;
                unsigned bd = sb + (unsigned)(ASZ * 4) +
                              (unsigned)(r * 128 + (((2 * ks + bcs) ^ (r & 7)) << 4));
                asm volatile(
                    "ldmatrix.sync.aligned.m8n8.x2.shared.b16 {%0,%1}, [%2];"
                    : "=r"(bf[nt][0]), "=r"(bf[nt][1])
                    : "r"(bd));
            }
#pragma unroll
            for (int mt = 0; mt < 4; mt++)
#pragma unroll
                for (int nt = 0; nt < 4; nt++)
                    asm volatile(
                        "mma.sync.aligned.m16n8k16.row.col.f32.f16.f16.f32 "
                        "{%0,%1,%2,%3}, {%4,%5,%6,%7}, {%8,%9}, {%0,%1,%2,%3};"
                        : "+f"(acc[mt][nt][0]), "+f"(acc[mt][nt][1]),
                          "+f"(acc[mt][nt][2]), "+f"(acc[mt][nt][3])
                        : "r"(a[mt][0]), "r"(a[mt][1]), "r"(a[mt][2]), "r"(a[mt][3]),
                          "r"(bf[nt][0]), "r"(bf[nt][1]));
        }
    }

    const int gg = lane >> 2, tt = lane & 3;
#pragma unroll
    for (int mt = 0; mt < 4; mt++) {
        int r = row0 + wm * 64 + mt * 16 + gg;
#pragma unroll
        for (int nt = 0; nt < 4; nt++) {
            int cc = col0 + wn * 32 + nt * 8 + 2 * tt;
            *(float2*)&C[(size_t)r * N + cc]       = make_float2(acc[mt][nt][0], acc[mt][nt][1]);
            *(float2*)&C[(size_t)(r + 8) * N + cc] = make_float2(acc[mt][nt][2], acc[mt][nt][3]);
        }
    }
}

// ============================================================================
// Depthwise conv(3) + bias + SiLU over xBC channels (cols 2048..8191 of zxbc)
// ============================================================================
__global__ void conv_silu_kernel(const float* __restrict__ zxbc,
                                 const float* __restrict__ cw,
                                 const float* __restrict__ cb,
                                 float* __restrict__ out)
{
    int ch = blockIdx.x * blockDim.x + threadIdx.x;
    int r  = blockIdx.y;
    if (ch >= CONVD) return;
    int l = r & (SEQ - 1);
    const float* col = zxbc + DMODEL + ch;
    float xm = (l > 0)       ? col[(size_t)(r - 1) * ZXB_LD] : 0.f;
    float x0 =                 col[(size_t)r       * ZXB_LD];
    float xp = (l < SEQ - 1) ? col[(size_t)(r + 1) * ZXB_LD] : 0.f;
    float v = fmaf(cw[ch * 3], xm, fmaf(cw[ch * 3 + 1], x0, fmaf(cw[ch * 3 + 2], xp, cb[ch])));
    out[(size_t)r * CONVD + ch] = v / (1.f + expf(-v));
}

// ============================================================================
// Per-chunk SSD. Y phase register-blocked: each thread computes 2 rows x 8
// cols (rows l, l+32), so per m-iter 2 LDS.32 + 2 LDS.128 feed 32 FMAs.
// ============================================================================
#define SPAD 68
#define SSD_SMEM (3 * 64 * SPAD * 4)

__global__ __launch_bounds__(256, 2) void ssd_chunk_kernel(const float* __restrict__ xbca,
                                                           float* __restrict__ ydiag,
                                                           float* __restrict__ cs)
{
    extern __shared__ float ssm[];
    float* Bs = ssm;
    float* Cs = ssm + 64 * SPAD;
    float* Gs = ssm + 2 * 64 * SPAD;

    int bid = blockIdx.x;
    int c  = bid & 63;
    int bh = bid >> 6;
    int h  = bh & 31;
    int b  = bh >> 5;
    size_t row0 = (size_t)(b * SEQ + c * CHUNK) * CONVD;
    int tid = threadIdx.x;

    for (int i = tid; i < 64 * 16; i += 256) {
        int l = i >> 4, q = (i & 15) * 4;
        *(float4*)&Bs[l * SPAD + q] = *(const float4*)&xbca[row0 + (size_t)l * CONVD + DMODEL + h * 64 + q];
        *(float4*)&Cs[l * SPAD + q] = *(const float4*)&xbca[row0 + (size_t)l * CONVD + 2 * DMODEL + h * 64 + q];
    }
    for (int i = tid; i < 64 * SPAD; i += 256) Gs[i] = 0.f;
    __syncthreads();

    // ---- G[l][m] = C[l] . B[m], lower triangle ----
    {
        const int l  = tid >> 2;
        const int m0 = tid & 3;
        for (int m = m0; m <= l; m += 4) {
            float4 s = make_float4(0.f, 0.f, 0.f, 0.f);
#pragma unroll 4
            for (int n = 0; n < 64; n += 4) {
                float4 cv = *(const float4*)&Cs[l * SPAD + n];
                float4 bv = *(const float4*)&Bs[m * SPAD + n];
                s.x = fmaf(cv.x, bv.x, s.x);
                s.y = fmaf(cv.y, bv.y, s.y);
                s.z = fmaf(cv.z, bv.z, s.z);
                s.w = fmaf(cv.w, bv.w, s.w);
            }
            Gs[l * SPAD + m] = (s.x + s.y) + (s.z + s.w);
        }
    }
    __syncthreads();

    // ---- load x over Cs ----
    for (int i = tid; i < 64 * 16; i += 256) {
        int ll = i >> 4, q = (i & 15) * 4;
        *(float4*)&Cs[ll * SPAD + q] = *(const float4*)&xbca[row0 + (size_t)ll * CONVD + h * 64 + q];
    }
    __syncthreads();

    // ---- Y[l][p] = sum_m G[l][m] x[m][p] ; 2 rows x 8 cols per thread ----
    {
        const int lt = tid & 31;          // rows lt, lt+32
        const int qt = tid >> 5;          // col block qt*8
        float4 a00 = make_float4(0.f,0.f,0.f,0.f), a01 = a00;
        float4 a10 = a00, a11 = a00;
        const float* gr0 = &Gs[lt * SPAD];
        const float* gr1 = &Gs[(lt + 32) * SPAD];
#pragma unroll 4
        for (int m = 0; m < 64; m++) {
            const float* xr = &Cs[m * SPAD + qt * 8];
            float4 x0 = *(const float4*)&xr[0];
            float4 x1 = *(const float4*)&xr[4];
            float g0 = gr0[m], g1 = gr1[m];
            a00.x = fmaf(g0, x0.x, a00.x); a00.y = fmaf(g0, x0.y, a00.y);
            a00.z = fmaf(g0, x0.z, a00.z); a00.w = fmaf(g0, x0.w, a00.w);
            a01.x = fmaf(g0, x1.x, a01.x); a01.y = fmaf(g0, x1.y, a01.y);
            a01.z = fmaf(g0, x1.z, a01.z); a01.w = fmaf(g0, x1.w, a01.w);
            a10.x = fmaf(g1, x0.x, a10.x); a10.y = fmaf(g1, x0.y, a10.y);
            a10.z = fmaf(g1, x0.z, a10.z); a10.w = fmaf(g1, x0.w, a10.w);
            a11.x = fmaf(g1, x1.x, a11.x); a11.y = fmaf(g1, x1.y, a11.y);
            a11.z = fmaf(g1, x1.z, a11.z); a11.w = fmaf(g1, x1.w, a11.w);
        }
        float* yr0 = &ydiag[(size_t)(b * SEQ + c * CHUNK + lt) * DMODEL + h * 64 + qt * 8];
        float* yr1 = &ydiag[(size_t)(b * SEQ + c * CHUNK + lt + 32) * DMODEL + h * 64 + qt * 8];
        *(float4*)&yr0[0] = a00;
        *(float4*)&yr0[4] = a01;
        *(float4*)&yr1[0] = a10;
        *(float4*)&yr1[4] = a11;
    }

    // ---- chunk state ----
    if (tid < 64) {
        float a = 0.f;
#pragma unroll 8
        for (int ll = 0; ll < 64; ll++)
            a = fmaf(Cs[ll * SPAD + tid], Bs[ll * SPAD + tid], a);
        cs[(size_t)bid * 64 + tid] = a;
    }
}

// ============================================================================
// Inter-chunk scan (constant decay exp(63*A_log[h]) per head)
// ============================================================================
__global__ void scan_kernel(const float* __restrict__ cs, const float* __restrict__ A_log,
                            float* __restrict__ prev)
{
    int bh = blockIdx.x;
    int h  = bh & 31;
    int n  = threadIdx.x;
    float d = expf(63.f * A_log[h]);
    float s = 0.f;
    for (int c = 0; c < NCHUNK; c++) {
        size_t idx = ((size_t)bh * NCHUNK + c) * 64 + n;
        prev[idx] = s;
        s = s * d + cs[idx];
    }
}

// ============================================================================
// Y = Y_diag + Y_off; gate with silu(z); RMSNorm. Output fp16.
// ============================================================================
__global__ __launch_bounds__(256) void combine_kernel(
    const float* __restrict__ ydiag, const float* __restrict__ zxbc,
    const float* __restrict__ xbca,  const float* __restrict__ prev,
    const float* __restrict__ rms_w, __half* __restrict__ yn)
{
    int r = blockIdx.x;
    int b = r >> 12;
    int l = r & (SEQ - 1);
    int c = l >> 6;

    __shared__ float sh_yoff[NHEADS];
    __shared__ float sh_red[8];

    int tid = threadIdx.x, warp = tid >> 5, lane = tid & 31;

    for (int h = warp; h < NHEADS; h += 8) {
        const float* Crow = xbca + (size_t)r * CONVD + 2 * DMODEL + h * 64;
        const float* pv   = prev + ((size_t)(b * NHEADS + h) * NCHUNK + c) * 64;
        int n0 = lane * 2;
        float v = Crow[n0] * pv[n0] + Crow[n0 + 1] * pv[n0 + 1];
#pragma unroll
        for (int o = 16; o; o >>= 1) v += __shfl_down_sync(0xffffffffu, v, o);
        if (lane == 0) sh_yoff[h] = v;
    }
    __syncthreads();

    float vals[8];
    float ss = 0.f;
#pragma unroll
    for (int j = 0; j < 8; j++) {
        int d = tid + j * 256;
        float z  = zxbc[(size_t)r * ZXB_LD + d];
        float sz = z / (1.f + expf(-z));
        float y  = (ydiag[(size_t)r * DMODEL + d] + sh_yoff[d >> 6]) * sz;
        vals[j] = y;
        ss += y * y;
    }
#pragma unroll
    for (int o = 16; o; o >>= 1) ss += __shfl_down_sync(0xffffffffu, ss, o);
    if (lane == 0) sh_red[warp] = ss;
    __syncthreads();
    if (tid == 0) {
        float t = 0.f;
#pragma unroll
        for (int w = 0; w < 8; w++) t += sh_red[w];
        sh_red[0] = rsqrtf(t / (float)DMODEL + RMS_EPS);
    }
    __syncthreads();
    float scale = sh_red[0];
#pragma unroll
    for (int j = 0; j < 8; j++) {
        int d = tid + j * 256;
        yn[(size_t)r * DMODEL + d] = __float2half_rn(vals[j] * scale * rms_w[d]);
    }
}

// ============================================================================
// launch
// ============================================================================
extern "C" void kernel_launch(void* const* d_in, const int* in_sizes, int n_in,
                              void* d_out, int out_size)
{
    const float* u      = (const float*)d_in[0];
    const float* W_in   = (const float*)d_in[1];
    const float* W_out  = (const float*)d_in[2];
    const float* conv_w = (const float*)d_in[3];
    const float* conv_b = (const float*)d_in[4];
    const float* A_log  = (const float*)d_in[5];
    const float* rms_w  = (const float*)d_in[6];
    float* out = (float*)d_out;

    float *zxbc, *xbca, *y, *cs, *prev;
    __half *yn, *ut, *wit, *wot;
    cudaGetSymbolAddress((void**)&zxbc, g_zxbc);
    cudaGetSymbolAddress((void**)&xbca, g_xbca);
    cudaGetSymbolAddress((void**)&y,    g_y);
    cudaGetSymbolAddress((void**)&yn,   g_yn);
    cudaGetSymbolAddress((void**)&cs,   g_cs);
    cudaGetSymbolAddress((void**)&prev, g_prev);
    cudaGetSymbolAddress((void**)&ut,   g_ut);
    cudaGetSymbolAddress((void**)&wit,  g_wit);
    cudaGetSymbolAddress((void**)&wot,  g_wot);

    static bool attr_done = false;
    if (!attr_done) {
        cudaFuncSetAttribute(gemm_tn_f16, cudaFuncAttributeMaxDynamicSharedMemorySize, GSMEM);
        cudaFuncSetAttribute(ssd_chunk_kernel, cudaFuncAttributeMaxDynamicSharedMemorySize, SSD_SMEM);
        attr_done = true;
    }

    // 0) convert operands to fp16
    {
        size_t n4u = (size_t)ROWS * DMODEL / 4;
        h_convert<<<(unsigned)((n4u + 255) / 256), 256>>>(u, ut, n4u);
        size_t n4w = (size_t)ZXB_LD * DMODEL / 4;
        h_convert<<<(unsigned)((n4w + 255) / 256), 256>>>(W_in, wit, n4w);
        size_t n4o = (size_t)DMODEL * DMODEL / 4;
        h_convert<<<(unsigned)((n4o + 255) / 256), 256>>>(W_out, wot, n4o);
    }
    // 1) zxbc = u @ W_in^T (first 8192 output cols; dt cols unused)
    gemm_tn_f16<<<dim3(ZXB_LD / 128, ROWS / 128), 256, GSMEM>>>(ut, wit, zxbc, ROWS, ZXB_LD, DMODEL);
    // 2) depthwise conv + silu
    conv_silu_kernel<<<dim3(CONVD / 256, ROWS), 256>>>(zxbc, conv_w, conv_b, xbca);
    // 3) per-chunk SSD
    ssd_chunk_kernel<<<BATCH * NHEADS * NCHUNK, 256, SSD_SMEM>>>(xbca, y, cs);
    // 4) inter-chunk scan
    scan_kernel<<<BATCH * NHEADS, 64>>>(cs, A_log, prev);
    // 5) Y_off + gate + rmsnorm (writes fp16)
    combine_kernel<<<ROWS, 256>>>(y, zxbc, xbca, prev, rms_w, yn);
    // 6) out = yn @ W_out^T
    gemm_tn_f16<<<dim3(DMODEL / 128, ROWS / 128), 256, GSMEM>>>(yn, wot, out, ROWS, DMODEL, DMODEL);
}